// round 17
// baseline (speedup 1.0000x reference)
#include <cuda_runtime.h>

typedef unsigned long long ull;

#define SEQ_T 512
#define NB    64
#define NIN   256
#define NH    512
#define NROW  2048                    // 4 gates * NH rows
#define NCOL  32768                   // SEQ_T * NB
#define NCTA  128                     // 32 j-groups x 4 b-groups
#define NTHR  384                     // 4 gemm warps + 8 recurrence warps
#define HSEQ_ELEMS (512L*64*512)      // 16777216
// smem: U2 135168B + h2 69632B + Ws 8448B + xs 8448B = 221696B
#define FUSED_SMEM 221696

// ---------------- device scratch (static: no allocations allowed) ----------
__device__ float    g_xp[(long)NROW * NCOL];   // [gate*512+j][t*64+b]
__device__ float    g_hbuf[2][NH * NB];        // [j][b] layout, double buffered
__device__ float    g_bias[NROW];              // Wb + Ub folded
__device__ unsigned g_bar[SEQ_T * 4];          // per-(step, b-group) barrier slots
__device__ unsigned g_xpcnt[SEQ_T];            // per-t xp tile counters (target 32)

// ---------------- f32x2 helpers (packed FFMA2 = 2x fp32 throughput) --------
__device__ __forceinline__ void fma2(ull &d, ull a, ull b){
    asm("fma.rn.f32x2 %0, %1, %2, %0;" : "+l"(d) : "l"(a), "l"(b));
}
__device__ __forceinline__ ull dup2(float v){
    ull r; asm("mov.b64 %0, {%1, %1};" : "=l"(r) : "f"(v)); return r;
}
__device__ __forceinline__ float2 unpack2(ull v){
    float2 r; asm("mov.b64 {%0, %1}, %2;" : "=f"(r.x), "=f"(r.y) : "l"(v)); return r;
}
// fast sigmoid / tanh via MUFU; validated rel_err 2.8e-7.
__device__ __forceinline__ float fsig(float x){
    return __fdividef(1.f, 1.f + __expf(-x));
}
__device__ __forceinline__ float ftanh(float x){
    return 1.f - __fdividef(2.f, __expf(2.f * x) + 1.f);
}
#define BAR_REC()  asm volatile("bar.sync 1, 256;" ::: "memory")
#define BAR_GEMM() asm volatile("bar.sync 2, 128;" ::: "memory")

// ---------------- init: h0 -> hbuf[0] ([j][b]), biases, zero counters ------
__global__ void init_kernel(const float* __restrict__ h0,
    const float* __restrict__ Wfb, const float* __restrict__ Ufb,
    const float* __restrict__ Wib, const float* __restrict__ Uib,
    const float* __restrict__ Wob, const float* __restrict__ Uob,
    const float* __restrict__ Wcb, const float* __restrict__ Ucb)
{
    int i = blockIdx.x * blockDim.x + threadIdx.x;   // 0..32767
    int j = i >> 6, b = i & 63;
    g_hbuf[0][i] = h0[b * NH + j];                   // transpose to [j][b]
    if (i < NROW) {
        int g = i >> 9, jj = i & 511;
        const float* Wb = (g==0)?Wfb:(g==1)?Wib:(g==2)?Wob:Wcb;
        const float* Ub = (g==0)?Ufb:(g==1)?Uib:(g==2)?Uob:Ucb;
        g_bias[i] = Wb[jj] + Ub[jj];
    }
    if (i < SEQ_T * 4) g_bar[i] = 0u;
    if (i < SEQ_T)     g_xpcnt[i] = 0u;
}

// ---------------- fused persistent kernel ----------------------------------
// tid 0..127  : xp producer (4 warps, wid 0-3, one per SMSP, LOW priority)
// tid 128..383: recurrence  (8 warps, wid 4-11 — EXACT R15 structure with
//               named barrier 1 instead of __syncthreads)
__global__ __launch_bounds__(NTHR, 1) void lstm_fused(
    const float* __restrict__ x,
    const float* __restrict__ Wf, const float* __restrict__ Wi,
    const float* __restrict__ Wo, const float* __restrict__ Wc,
    const float* __restrict__ Uf, const float* __restrict__ Ui,
    const float* __restrict__ Uo, const float* __restrict__ Uc,
    const float* __restrict__ c0, float* __restrict__ out)
{
    extern __shared__ float smem[];
    float2* U2 = (float2*)smem;                  // [k*33 + cp]
    float2* h2 = (float2*)(smem + 33792);        // [k*17 + b]
    float*  Ws = smem + 51200;                   // [k*66 + r], 32k x 64r
    float*  xs = smem + 53312;                   // [k*66 + c], 32k x 64c

    const int tid = threadIdx.x;

    if (tid < 128) {
        // ================== xp GEMM producer ==================
        // tiles 64r x 64c x 256k; tile g = t*32 + ry -> CTA g%128, seq g/128.
        // Each t's 32 row-tiles run on 32 CTAs concurrently, in t order.
        const int rowg = tid >> 3;               // 0..15 (4 rows each)
        const int colg = tid & 7;                // 0..7  (8 cols each)
        for (int s = 0; s < 128; s++) {
            int g  = s * 128 + (int)blockIdx.x;
            int t  = g >> 5, ry = g & 31;
            int r0 = ry * 64;
            int gate = r0 >> 9;
            const float* Wg = (gate==0)?Wf:(gate==1)?Wi:(gate==2)?Wo:Wc;
            int wr0 = r0 & 511;
            long c0l = (long)t * 64;

            ull acc[4][4];
            #pragma unroll
            for (int i = 0; i < 4; i++)
                #pragma unroll
                for (int q = 0; q < 4; q++) acc[i][q] = 0ull;

            for (int kc = 0; kc < NIN; kc += 32) {
                BAR_GEMM();     // previous chunk fully consumed
                #pragma unroll
                for (int it = 0; it < 4; it++) {
                    int idx = tid + it * 128;    // 0..511
                    int row = idx >> 3, k4 = (idx & 7) * 4;
                    float4 wv = __ldg((const float4*)&Wg[(wr0+row)*NIN + kc + k4]);
                    Ws[(k4+0)*66+row]=wv.x; Ws[(k4+1)*66+row]=wv.y;
                    Ws[(k4+2)*66+row]=wv.z; Ws[(k4+3)*66+row]=wv.w;
                    float4 xv = __ldg((const float4*)&x[(c0l+row)*NIN + kc + k4]);
                    xs[(k4+0)*66+row]=xv.x; xs[(k4+1)*66+row]=xv.y;
                    xs[(k4+2)*66+row]=xv.z; xs[(k4+3)*66+row]=xv.w;
                }
                BAR_GEMM();
                #pragma unroll 4
                for (int k = 0; k < 32; k++) {
                    const float* wr = Ws + k*66 + rowg*4;
                    ull w0 = dup2(wr[0]), w1 = dup2(wr[1]);
                    ull w2 = dup2(wr[2]), w3 = dup2(wr[3]);
                    const ull* xpp = (const ull*)(xs + k*66 + colg*8);
                    ull p0 = xpp[0], p1 = xpp[1], p2 = xpp[2], p3 = xpp[3];
                    fma2(acc[0][0], w0, p0); fma2(acc[1][0], w1, p0);
                    fma2(acc[2][0], w2, p0); fma2(acc[3][0], w3, p0);
                    fma2(acc[0][1], w0, p1); fma2(acc[1][1], w1, p1);
                    fma2(acc[2][1], w2, p1); fma2(acc[3][1], w3, p1);
                    fma2(acc[0][2], w0, p2); fma2(acc[1][2], w1, p2);
                    fma2(acc[2][2], w2, p2); fma2(acc[3][2], w3, p2);
                    fma2(acc[0][3], w0, p3); fma2(acc[1][3], w1, p3);
                    fma2(acc[2][3], w2, p3); fma2(acc[3][3], w3, p3);
                }
            }
            // epilogue: +bias, store 8 consecutive cols per row
            #pragma unroll
            for (int rr = 0; rr < 4; rr++) {
                int r = r0 + rowg * 4 + rr;
                float bias = g_bias[r];
                float2 o0 = unpack2(acc[rr][0]); o0.x += bias; o0.y += bias;
                float2 o1 = unpack2(acc[rr][1]); o1.x += bias; o1.y += bias;
                float2 o2 = unpack2(acc[rr][2]); o2.x += bias; o2.y += bias;
                float2 o3 = unpack2(acc[rr][3]); o3.x += bias; o3.y += bias;
                float* dst = &g_xp[(long)r * NCOL + c0l + colg * 8];
                *(float4*)(dst)     = make_float4(o0.x, o0.y, o1.x, o1.y);
                *(float4*)(dst + 4) = make_float4(o2.x, o2.y, o3.x, o3.y);
            }
            BAR_GEMM();         // all 128 threads' stores issued
            if (tid == 0) {     // proven release pattern (bar + one fence)
                __threadfence();
                atomicAdd(&g_xpcnt[t], 1u);
            }
        }
        return;                 // producer warps exit; recurrence continues
    }

    // ================== recurrence (EXACT R15 core) ==================
    const int rtid = tid - 128;
    const int jg   = blockIdx.x & 31;
    const int bg   = blockIdx.x >> 5;
    const int w    = rtid >> 5, lane = rtid & 31;
    const int cg   = lane & 7, bg2 = lane >> 3;
    const int jl   = rtid & 15, bl = rtid >> 4;
    const int lq   = lane & 3, rl = lane >> 2;

    {
        const float* Uw[4] = {Uf, Ui, Uo, Uc};
        for (int idx = rtid; idx < 512 * 32; idx += 256) {
            int k = idx & 511, cp = idx >> 9;
            const float* Ug = Uw[cp >> 3];
            int j0 = jg * 16 + ((2 * cp) & 15);
            U2[k * 33 + cp] = make_float2(Ug[j0 * NH + k], Ug[(j0 + 1) * NH + k]);
        }
    }
    float creg = c0[(bg * 16 + bl) * NH + jg * 16 + jl];
    long xbase[4];
    #pragma unroll
    for (int g = 0; g < 4; g++)
        xbase[g] = ((long)(g * NH + jg * 16 + jl) << 15) + bg * 16 + bl;

    const float2* ub = U2 + cg;
    const float2* hb = h2 + bg2;
    float2* stash = h2 + w * 1088;
    const long obase = (long)(bg * 16 + bl) * 512 + jg * 16 + jl;

    // wait for xp(0) while U2 settles (rtid0 spin, proven form)
    if (rtid == 0) {
        volatile unsigned* xq = &g_xpcnt[0];
        while (*xq < 32u) { }
        __threadfence();
    }
    BAR_REC();   // U2 ready + xp(0) ready

    for (int t = 0; t < SEQ_T; t++) {
        // xp slice (written in-kernel -> must be L2-coherent ldcg, not __ldg)
        float xg0 = __ldcg(&g_xp[xbase[0] + t * 64]);
        float xg1 = __ldcg(&g_xp[xbase[1] + t * 64]);
        float xg2 = __ldcg(&g_xp[xbase[2] + t * 64]);
        float xg3 = __ldcg(&g_xp[xbase[3] + t * 64]);

        const float* hsrc = g_hbuf[t & 1] + bg * 16;
        #pragma unroll
        for (int i = 0; i < 8; i++) {
            int r = w * 64 + i * 8 + rl;
            float4 v = __ldcg((const float4*)(hsrc + r * 64 + lq * 4));
            float2* d = h2 + r * 17 + lq * 4;
            d[0] = make_float2(v.x, v.x); d[1] = make_float2(v.y, v.y);
            d[2] = make_float2(v.z, v.z); d[3] = make_float2(v.w, v.w);
        }
        __syncwarp();

        ull acc[4][4];
        #pragma unroll
        for (int i = 0; i < 4; i++)
            #pragma unroll
            for (int q = 0; q < 4; q++) acc[i][q] = 0ull;
        const int k0 = w * 64;
        #pragma unroll 4
        for (int k = k0; k < k0 + 64; k++) {
            const ull* up = (const ull*)(ub + k * 33);
            ull u0 = up[0], u1 = up[8], u2 = up[16], u3 = up[24];
            const ull* hp = (const ull*)(hb + k * 17);
            ull p0 = hp[0], p1 = hp[4], p2 = hp[8], p3 = hp[12];
            fma2(acc[0][0], u0, p0); fma2(acc[1][0], u1, p0);
            fma2(acc[2][0], u2, p0); fma2(acc[3][0], u3, p0);
            fma2(acc[0][1], u0, p1); fma2(acc[1][1], u1, p1);
            fma2(acc[2][1], u2, p1); fma2(acc[3][1], u3, p1);
            fma2(acc[0][2], u0, p2); fma2(acc[1][2], u1, p2);
            fma2(acc[2][2], u2, p2); fma2(acc[3][2], u3, p2);
            fma2(acc[0][3], u0, p3); fma2(acc[1][3], u1, p3);
            fma2(acc[2][3], u2, p3); fma2(acc[3][3], u3, p3);
        }
        __syncwarp();
        #pragma unroll
        for (int i = 0; i < 4; i++)
            #pragma unroll
            for (int q = 0; q < 4; q++)
                *(ull*)&stash[(cg + 8 * i) * 17 + bg2 + 4 * q] = acc[i][q];
        BAR_REC();

        float p[4];
        #pragma unroll
        for (int g = 0; g < 4; g++) {
            int c = g * 16 + jl, cp = c >> 1, hf = c & 1;
            float s = 0.f;
            #pragma unroll
            for (int ww = 0; ww < 8; ww++)
                s += ((const float*)(h2 + ww * 1088 + cp * 17 + bl))[hf];
            p[g] = s;
        }
        p[0] += xg0; p[1] += xg1; p[2] += xg2; p[3] += xg3;
        float fg = fsig(p[0]);
        float ig = fsig(p[1]);
        float og = fsig(p[2]);
        float gg = ftanh(p[3]);
        creg = fg * creg + ig * gg;
        float hv = og * ftanh(creg);

        g_hbuf[(t + 1) & 1][(jg * 16 + jl) * 64 + bg * 16 + bl] = hv;

        BAR_REC();   // all h writes issued (cta-scope ordering)
        if (t < SEQ_T - 1) {
            if (rtid == 0) {                // gpu-scope release by one thread
                __threadfence();            // cumulative over the bar above
                atomicAdd(&g_bar[t * 4 + bg], 1u);
            }
        }

        // h_seq store (coalesced: jl fast), overlaps the barrier wait
        out[(long)t * 32768 + obase] = hv;
        if (t == SEQ_T - 1) {
            out[HSEQ_ELEMS + obase] = hv;
            out[HSEQ_ELEMS + 32768 + obase] = creg;
        } else {
            if (rtid == 0) {
                volatile unsigned* bp_ = &g_bar[t * 4 + bg];
                while (*bp_ < 32u) { }
                volatile unsigned* xq_ = &g_xpcnt[t + 1];   // xp gate (cheap)
                while (*xq_ < 32u) { }
                __threadfence();            // acquire
            }
            BAR_REC();                      // release barrier result + h2 reuse
        }
    }
}

// ---------------- launch ----------------------------------------------------
extern "C" void kernel_launch(void* const* d_in, const int* in_sizes, int n_in,
                              void* d_out, int out_size)
{
    const float* x    = (const float*)d_in[0];
    const float* h0   = (const float*)d_in[1];
    const float* c0   = (const float*)d_in[2];
    const float* Wf_w = (const float*)d_in[3];
    const float* Wf_b = (const float*)d_in[4];
    const float* Uf_w = (const float*)d_in[5];
    const float* Uf_b = (const float*)d_in[6];
    const float* Wi_w = (const float*)d_in[7];
    const float* Wi_b = (const float*)d_in[8];
    const float* Ui_w = (const float*)d_in[9];
    const float* Ui_b = (const float*)d_in[10];
    const float* Wo_w = (const float*)d_in[11];
    const float* Wo_b = (const float*)d_in[12];
    const float* Uo_w = (const float*)d_in[13];
    const float* Uo_b = (const float*)d_in[14];
    const float* Wc_w = (const float*)d_in[15];
    const float* Wc_b = (const float*)d_in[16];
    const float* Uc_w = (const float*)d_in[17];
    const float* Uc_b = (const float*)d_in[18];
    float* out = (float*)d_out;

    cudaFuncSetAttribute(lstm_fused,
        cudaFuncAttributeMaxDynamicSharedMemorySize, FUSED_SMEM);

    init_kernel<<<128, 256>>>(h0, Wf_b, Uf_b, Wi_b, Ui_b,
                              Wo_b, Uo_b, Wc_b, Uc_b);

    lstm_fused<<<NCTA, NTHR, FUSED_SMEM>>>(
        x, Wf_w, Wi_w, Wo_w, Wc_w,
        Uf_w, Ui_w, Uo_w, Uc_w, c0, out);
}